// round 15
// baseline (speedup 1.0000x reference)
#include <cuda_runtime.h>
#include <cuda_fp16.h>
#include <cuda_bf16.h>
#include <cstdint>
#include <cstddef>

#define HID 128
#define MAX_NODES 100096

// fp16 table: row n = [fp16(emb[n]@W1[:128]+b1) | fp16(emb[n]@W1[128:])]
__device__ __half g_table[(size_t)MAX_NODES * 256];
__device__ __half g_W2h[HID];
__device__ int g_is64;

#define PITCH 68
#define SB_ELE (64 * PITCH)            // 4352 b32 per 64-col N-tile
// staged fp16 W1 in the exact padded smem layout, 4 N-tiles of 64
__device__ uint32_t g_sB[4 * SB_ELE];

// ---------------------------------------------------------------------------
// helpers
// ---------------------------------------------------------------------------
__device__ __forceinline__ uint32_t smem_u32(const void* p) {
    uint32_t a;
    asm("{ .reg .u64 t; cvta.to.shared.u64 t, %1; cvt.u32.u64 %0, t; }" : "=r"(a) : "l"(p));
    return a;
}

__device__ __forceinline__ uint32_t pack_h2(float x0, float x1) {
    __half2 p = __floats2half2_rn(x0, x1);  // .x -> low half
    return *reinterpret_cast<uint32_t*>(&p);
}

__device__ __forceinline__ void mma_f16(float* d, const uint32_t* a, const uint32_t* b) {
    asm volatile(
        "mma.sync.aligned.m16n8k16.row.col.f32.f16.f16.f32 "
        "{%0,%1,%2,%3}, {%4,%5,%6,%7}, {%8,%9}, {%0,%1,%2,%3};\n"
        : "+f"(d[0]), "+f"(d[1]), "+f"(d[2]), "+f"(d[3])
        : "r"(a[0]), "r"(a[1]), "r"(a[2]), "r"(a[3]), "r"(b[0]), "r"(b[1]));
}

__device__ __forceinline__ void ldsm_x4(uint32_t* r, uint32_t addr) {
    asm volatile("ldmatrix.sync.aligned.m8n8.x4.shared.b16 {%0,%1,%2,%3}, [%4];"
                 : "=r"(r[0]), "=r"(r[1]), "=r"(r[2]), "=r"(r[3]) : "r"(addr));
}

// forced-order non-coherent 16B global load (keeps all gathers in flight)
__device__ __forceinline__ uint4 ldg_nc_v4(const void* p) {
    uint4 v;
    asm volatile("ld.global.nc.v4.u32 {%0,%1,%2,%3}, [%4];"
                 : "=r"(v.x), "=r"(v.y), "=r"(v.z), "=r"(v.w) : "l"(p));
    return v;
}

// ---------------------------------------------------------------------------
// Prep: W1 -> fp16 staging (padded [n][kb] layout, 4 N-tiles of 64),
// W2 -> fp16, plus index-width detection (one launch for all).
// ---------------------------------------------------------------------------
__global__ void prep_kernel(const float* __restrict__ W1,
                            const float* __restrict__ W2,
                            const uint32_t* __restrict__ src)
{
    int i = blockIdx.x * blockDim.x + threadIdx.x;  // 0..16383
    if (i < 256 * 64) {
        int n = i & 255;
        int kb = i >> 8;             // b32 index along K (k = 2*kb)
        int k = kb * 2;
        float w0, w1;
        if (n < HID) {
            w0 = W1[k * HID + n];
            w1 = W1[(k + 1) * HID + n];
        } else {
            w0 = W1[(HID + k) * HID + (n - HID)];
            w1 = W1[(HID + k + 1) * HID + (n - HID)];
        }
        int idx = (n >> 6) * SB_ELE + (n & 63) * PITCH + kb;
        g_sB[idx] = pack_h2(w0, w1);
    }
    if (i < HID) g_W2h[i] = __float2half_rn(W2[i]);
    if (i == 0) {
        int is64 = 1;
        for (int j = 1; j < 32; j += 2)
            if (src[j] != 0u) { is64 = 0; break; }
        g_is64 = is64;
    }
}

// ---------------------------------------------------------------------------
// Precompute: T[n][256] = fp16([emb@W1[:128]+b1 | emb@W1[128:]])
// Single-pass fp16 MMA, fp32 accumulate, b1 folded into acc init.
// BLOCK_M=64, 8 warps = 2(M) x 4(N), two 128-col passes over fused N=256.
// __launch_bounds__(256, 3): 85-reg budget removes the spills the
// 64-reg cap of (256,4) forced into the unrolled MMA loop; 24 warps/SM.
// Per pass: [bar, MMA, bar, copy-next-pair || epilogue].
// Epilogue: 3-shfl quad transpose -> coalesced STG.128.
// ---------------------------------------------------------------------------
#define BLOCK_M 64
#define SA_ELE (BLOCK_M * PITCH)           // 4352 b32
#define SB_PAIR (2 * SB_ELE)               // 8704 b32 (two 64-col tiles)
#define SM_B1_OFF (SA_ELE + SB_PAIR)       // b32 offset of b1 (128 floats)
#define SMEM_BYTES ((SA_ELE + SB_PAIR + HID) * 4)   // 52736 B

__global__ void __launch_bounds__(256, 3) precompute_kernel(
    const float* __restrict__ emb, const float* __restrict__ b1, int n_nodes)
{
    extern __shared__ uint32_t sm[];
    uint32_t* sA = sm;
    uint32_t* sB = sm + SA_ELE;            // pair of B tiles
    float* sb1 = reinterpret_cast<float*>(sm + SM_B1_OFF);

    const int tid = threadIdx.x;
    const int m0 = blockIdx.x * BLOCK_M;

    if (tid < HID) sb1[tid] = b1[tid];

    // ---- A tile: 64 rows x 128 K floats -> fp16 pairs (once) ----
    for (int i = tid; i < BLOCK_M * (HID / 4); i += 256) {
        int row = i >> 5;
        int c4 = (i & 31) * 4;
        float4 v = make_float4(0.f, 0.f, 0.f, 0.f);
        if (m0 + row < n_nodes)
            v = *reinterpret_cast<const float4*>(emb + (size_t)(m0 + row) * HID + c4);
        int base = row * PITCH + c4 / 2;   // even -> 8B aligned
        *reinterpret_cast<uint2*>(sA + base) =
            make_uint2(pack_h2(v.x, v.y), pack_h2(v.z, v.w));
    }

    // ---- copy B pair 0 (tiles 0,1) ----
    {
        const uint4* s = reinterpret_cast<const uint4*>(g_sB);
        uint4* d = reinterpret_cast<uint4*>(sB);
        for (int i = tid; i < SB_PAIR / 4; i += 256)
            d[i] = s[i];
    }

    const int warp = tid >> 5, lane = tid & 31;
    const int wm = warp & 1;    // 2 M slabs of 32 rows
    const int wn = warp >> 1;   // 4 N slabs of 32 cols (128 cols per pass)
    const int gid = lane >> 2, tig = lane & 3;

    const int a_row = (lane & 15);
    const int a_kb  = (lane >> 4) * 4;
    const int b_n  = (lane & 7) + (lane >> 4) * 8;
    const int b_kb = ((lane >> 3) & 1) * 4;

    const uint32_t sA_a = smem_u32(sA), sB_a = smem_u32(sB);
    const uint32_t sBslab_a = sB_a + (uint32_t)((wn >> 1) * SB_ELE
                                                + (wn & 1) * 32 * PITCH) * 4u;

#pragma unroll 1
    for (int j = 0; j < 2; j++) {
        __syncthreads();   // B pair j visible to all warps

        // ---- acc init: b1 for cols < 128 (j==0), else 0 ----
        float acc[2][4][4];
#pragma unroll
        for (int ni = 0; ni < 4; ni++) {
            float c0 = 0.f, c1 = 0.f;
            if (j == 0) {
                int gcol = wn * 32 + ni * 8 + 2 * tig;
                float2 bb = *reinterpret_cast<const float2*>(sb1 + gcol);
                c0 = bb.x; c1 = bb.y;
            }
#pragma unroll
            for (int mi = 0; mi < 2; mi++) {
                acc[mi][ni][0] = c0; acc[mi][ni][1] = c1;
                acc[mi][ni][2] = c0; acc[mi][ni][3] = c1;
            }
        }

#pragma unroll
        for (int ks = 0; ks < HID / 16; ks++) {
            const int kb0 = ks * 8;
            uint32_t af[2][4], bf[2][4];
#pragma unroll
            for (int mi = 0; mi < 2; mi++) {
                uint32_t off = ((wm * 32 + mi * 16 + a_row) * PITCH + kb0 + a_kb) * 4u;
                ldsm_x4(af[mi], sA_a + off);
            }
#pragma unroll
            for (int pr = 0; pr < 2; pr++) {
                uint32_t off = ((pr * 16 + b_n) * PITCH + kb0 + b_kb) * 4u;
                ldsm_x4(bf[pr], sBslab_a + off);
            }
#pragma unroll
            for (int mi = 0; mi < 2; mi++)
#pragma unroll
                for (int ni = 0; ni < 4; ni++)
                    mma_f16(acc[mi][ni], af[mi], &bf[ni >> 1][(ni & 1) * 2]);
        }

        __syncthreads();   // all warps' reads of pair j complete

        // ---- copy B pair 1 (overlaps the epilogue STGs below) ----
        if (j == 0) {
            const uint4* s = reinterpret_cast<const uint4*>(g_sB + SB_PAIR);
            uint4* d = reinterpret_cast<uint4*>(sB);
            for (int i = tid; i < SB_PAIR / 4; i += 256)
                d[i] = s[i];
        }

        // ---- epilogue: pack fp16, quad-transpose, coalesced STG.128 ----
        const int cb = j * 128 + wn * 32 + 8 * tig;
#pragma unroll
        for (int mi = 0; mi < 2; mi++) {
#pragma unroll
            for (int rh = 0; rh < 2; rh++) {
                uint32_t v[4];   // v[ni] = half2(acc[mi][ni][2rh], [2rh+1])
#pragma unroll
                for (int ni = 0; ni < 4; ni++)
                    v[ni] = pack_h2(acc[mi][ni][2 * rh], acc[mi][ni][2 * rh + 1]);
                uint32_t r1 = __shfl_xor_sync(0xFFFFFFFFu, v[tig ^ 1], 1);
                uint32_t r2 = __shfl_xor_sync(0xFFFFFFFFu, v[tig ^ 2], 2);
                uint32_t r3 = __shfl_xor_sync(0xFFFFFFFFu, v[tig ^ 3], 3);
                uint32_t ww[4];
                ww[tig] = v[tig];
                ww[tig ^ 1] = r1;
                ww[tig ^ 2] = r2;
                ww[tig ^ 3] = r3;
                int row = m0 + wm * 32 + mi * 16 + rh * 8 + gid;
                if (row < n_nodes) {
                    *reinterpret_cast<uint4*>(&g_table[(size_t)row * 256 + cb]) =
                        make_uint4(ww[0], ww[1], ww[2], ww[3]);
                }
            }
        }
    }
}

// ---------------------------------------------------------------------------
// Edge kernel: 8 edges per warp (half-warp owns 4 consecutive edges).
// All 8 table gathers issued as ordered asm ld.global.nc.v4 BEFORE any
// compute. hfma2_relu fused add+relu, fp32 reduce: 2 butterfly rounds +
// 3-shfl transpose-reduce, predicated per-lane 4B stores.
// ---------------------------------------------------------------------------
__device__ __forceinline__ __half2 u2h(uint32_t x) {
    return *reinterpret_cast<__half2*>(&x);
}

__device__ __forceinline__ float dot8_relu(uint4 a, uint4 c, uint4 w) {
    const __half2 one = __float2half2_rn(1.f);
    __half2 r0 = __hfma2_relu(u2h(a.x), one, u2h(c.x));
    __half2 r1 = __hfma2_relu(u2h(a.y), one, u2h(c.y));
    __half2 r2 = __hfma2_relu(u2h(a.z), one, u2h(c.z));
    __half2 r3 = __hfma2_relu(u2h(a.w), one, u2h(c.w));
    __half2 p0 = __hmul2(r0, u2h(w.x));
    p0 = __hfma2(r1, u2h(w.y), p0);
    __half2 p1 = __hmul2(r2, u2h(w.z));
    p1 = __hfma2(r3, u2h(w.w), p1);
    float2 f0 = __half22float2(p0);
    float2 f1 = __half22float2(p1);
    return (f0.x + f0.y) + (f1.x + f1.y);
}

__global__ void __launch_bounds__(256) edge_kernel(
    const void* __restrict__ srcv, const void* __restrict__ tgtv,
    const float* __restrict__ b2, float* __restrict__ out, int E)
{
    int gw = (int)((blockIdx.x * blockDim.x + threadIdx.x) >> 5);
    int base = gw * 8;
    if (base >= E) return;
    int lane = threadIdx.x & 31;
    int half = lane >> 4, l16 = lane & 15;
    int tig = lane & 3;

    int e0 = base + half * 4;             // this half's first edge (mult of 4)
    bool full = (e0 + 4 <= E);

    uint32_t s[4], t[4];
    if (g_is64) {
        const long long* sp = (const long long*)srcv;
        const long long* tp = (const long long*)tgtv;
        if (full) {
            longlong2 s01 = *reinterpret_cast<const longlong2*>(sp + e0);
            longlong2 s23 = *reinterpret_cast<const longlong2*>(sp + e0 + 2);
            longlong2 t01 = *reinterpret_cast<const longlong2*>(tp + e0);
            longlong2 t23 = *reinterpret_cast<const longlong2*>(tp + e0 + 2);
            s[0] = (uint32_t)s01.x; s[1] = (uint32_t)s01.y;
            s[2] = (uint32_t)s23.x; s[3] = (uint32_t)s23.y;
            t[0] = (uint32_t)t01.x; t[1] = (uint32_t)t01.y;
            t[2] = (uint32_t)t23.x; t[3] = (uint32_t)t23.y;
        } else {
#pragma unroll
            for (int e = 0; e < 4; e++) {
                int idx = (e0 + e < E) ? e0 + e : E - 1;
                s[e] = (uint32_t)sp[idx];
                t[e] = (uint32_t)tp[idx];
            }
        }
    } else {
        const int* sp = (const int*)srcv;
        const int* tp = (const int*)tgtv;
        if (full) {
            uint4 sv = *reinterpret_cast<const uint4*>(sp + e0);
            uint4 tv = *reinterpret_cast<const uint4*>(tp + e0);
            s[0] = sv.x; s[1] = sv.y; s[2] = sv.z; s[3] = sv.w;
            t[0] = tv.x; t[1] = tv.y; t[2] = tv.z; t[3] = tv.w;
        } else {
#pragma unroll
            for (int e = 0; e < 4; e++) {
                int idx = (e0 + e < E) ? e0 + e : E - 1;
                s[e] = (uint32_t)sp[idx];
                t[e] = (uint32_t)tp[idx];
            }
        }
    }

    const __half* tab = g_table;
    const uint32_t col = (uint32_t)(l16 * 8);
    // all 8 gathers issued back-to-back (ordered volatile asm -> MLP=8)
    uint4 A[4], C[4];
#pragma unroll
    for (int e = 0; e < 4; e++)
        A[e] = ldg_nc_v4(tab + s[e] * 256u + col);
#pragma unroll
    for (int e = 0; e < 4; e++)
        C[e] = ldg_nc_v4(tab + t[e] * 256u + 128u + col);
    const uint4 w = __ldg(reinterpret_cast<const uint4*>(g_W2h + col));

    float sum[4];
#pragma unroll
    for (int e = 0; e < 4; e++)
        sum[e] = dot8_relu(A[e], C[e], w);

    // 2 butterfly rounds: each lane ends with partial over lanes == l16 (mod 4)
#pragma unroll
    for (int off = 8; off >= 4; off >>= 1) {
#pragma unroll
        for (int e = 0; e < 4; e++)
            sum[e] += __shfl_xor_sync(0xFFFFFFFFu, sum[e], off);
    }
    // transpose-reduce across the quad: lane tig accumulates edge tig's total
    float tot = sum[tig];
    tot += __shfl_xor_sync(0xFFFFFFFFu, sum[tig ^ 1], 1);
    tot += __shfl_xor_sync(0xFFFFFFFFu, sum[tig ^ 2], 2);
    tot += __shfl_xor_sync(0xFFFFFFFFu, sum[tig ^ 3], 3);

    if (l16 < 4) {
        int eo = e0 + tig;
        if (eo < E) out[eo] = tot + __ldg(b2);
    }
}

// ---------------------------------------------------------------------------
// launch
// ---------------------------------------------------------------------------
extern "C" void kernel_launch(void* const* d_in, const int* in_sizes, int n_in,
                              void* d_out, int out_size)
{
    const float* emb = (const float*)d_in[0];
    const void* src = d_in[1];
    const void* tgt = d_in[2];

    int base = (n_in > 3 && in_sizes[3] == 2 * HID * HID) ? 3 : 4;
    const float* W1 = (const float*)d_in[base];
    const float* b1 = (const float*)d_in[base + 1];
    const float* W2 = (const float*)d_in[base + 2];
    const float* b2 = (const float*)d_in[base + 3];

    int n_nodes = in_sizes[0] / HID;
    int E = in_sizes[1];

    prep_kernel<<<64, 256>>>(W1, W2, (const uint32_t*)src);

    cudaFuncSetAttribute(precompute_kernel,
                         cudaFuncAttributeMaxDynamicSharedMemorySize, SMEM_BYTES);
    int pgrid = (n_nodes + BLOCK_M - 1) / BLOCK_M;
    precompute_kernel<<<pgrid, 256, SMEM_BYTES>>>(emb, b1, n_nodes);

    // 8 warps/block, 8 edges/warp
    int warps_needed = (E + 7) / 8;
    int nblocks = (warps_needed + 7) / 8;
    edge_kernel<<<nblocks, 256>>>(src, tgt, b2, (float*)d_out, E);
}

// round 16
// speedup vs baseline: 1.0370x; 1.0370x over previous
#include <cuda_runtime.h>
#include <cuda_fp16.h>
#include <cuda_bf16.h>
#include <cstdint>
#include <cstddef>

#define HID 128
#define MAX_NODES 100096

// fp16 table: row n = [fp16(emb[n]@W1[:128]+b1) | fp16(emb[n]@W1[128:])]
__device__ __half g_table[(size_t)MAX_NODES * 256];
__device__ __half g_W2h[HID];
__device__ int g_is64;

#define PITCH 68
#define SB_ELE (64 * PITCH)            // 4352 b32 per 64-col N-tile
// staged fp16 W1 in the exact padded smem layout, 4 N-tiles of 64
__device__ uint32_t g_sB[4 * SB_ELE];

// ---------------------------------------------------------------------------
// helpers
// ---------------------------------------------------------------------------
__device__ __forceinline__ uint32_t smem_u32(const void* p) {
    uint32_t a;
    asm("{ .reg .u64 t; cvta.to.shared.u64 t, %1; cvt.u32.u64 %0, t; }" : "=r"(a) : "l"(p));
    return a;
}

__device__ __forceinline__ uint32_t pack_h2(float x0, float x1) {
    __half2 p = __floats2half2_rn(x0, x1);  // .x -> low half
    return *reinterpret_cast<uint32_t*>(&p);
}

__device__ __forceinline__ void mma_f16(float* d, const uint32_t* a, const uint32_t* b) {
    asm volatile(
        "mma.sync.aligned.m16n8k16.row.col.f32.f16.f16.f32 "
        "{%0,%1,%2,%3}, {%4,%5,%6,%7}, {%8,%9}, {%0,%1,%2,%3};\n"
        : "+f"(d[0]), "+f"(d[1]), "+f"(d[2]), "+f"(d[3])
        : "r"(a[0]), "r"(a[1]), "r"(a[2]), "r"(a[3]), "r"(b[0]), "r"(b[1]));
}

__device__ __forceinline__ void ldsm_x4(uint32_t* r, uint32_t addr) {
    asm volatile("ldmatrix.sync.aligned.m8n8.x4.shared.b16 {%0,%1,%2,%3}, [%4];"
                 : "=r"(r[0]), "=r"(r[1]), "=r"(r[2]), "=r"(r[3]) : "r"(addr));
}

// forced-order non-coherent 16B global load (keeps all gathers in flight)
__device__ __forceinline__ uint4 ldg_nc_v4(const void* p) {
    uint4 v;
    asm volatile("ld.global.nc.v4.u32 {%0,%1,%2,%3}, [%4];"
                 : "=r"(v.x), "=r"(v.y), "=r"(v.z), "=r"(v.w) : "l"(p));
    return v;
}

// evict-first 16B load (read-once streams: indices)
__device__ __forceinline__ uint4 ldg_cs_v4(const void* p) {
    uint4 v;
    asm volatile("ld.global.cs.v4.u32 {%0,%1,%2,%3}, [%4];"
                 : "=r"(v.x), "=r"(v.y), "=r"(v.z), "=r"(v.w) : "l"(p));
    return v;
}

// streaming 4B store (write-once output)
__device__ __forceinline__ void stg_cs_f32(float* p, float v) {
    asm volatile("st.global.cs.f32 [%0], %1;" :: "l"(p), "f"(v) : "memory");
}

// ---------------------------------------------------------------------------
// Prep: W1 -> fp16 staging (padded [n][kb] layout, 4 N-tiles of 64),
// W2 -> fp16, plus index-width detection (one launch for all).
// ---------------------------------------------------------------------------
__global__ void prep_kernel(const float* __restrict__ W1,
                            const float* __restrict__ W2,
                            const uint32_t* __restrict__ src)
{
    int i = blockIdx.x * blockDim.x + threadIdx.x;  // 0..16383
    if (i < 256 * 64) {
        int n = i & 255;
        int kb = i >> 8;             // b32 index along K (k = 2*kb)
        int k = kb * 2;
        float w0, w1;
        if (n < HID) {
            w0 = W1[k * HID + n];
            w1 = W1[(k + 1) * HID + n];
        } else {
            w0 = W1[(HID + k) * HID + (n - HID)];
            w1 = W1[(HID + k + 1) * HID + (n - HID)];
        }
        int idx = (n >> 6) * SB_ELE + (n & 63) * PITCH + kb;
        g_sB[idx] = pack_h2(w0, w1);
    }
    if (i < HID) g_W2h[i] = __float2half_rn(W2[i]);
    if (i == 0) {
        int is64 = 1;
        for (int j = 1; j < 32; j += 2)
            if (src[j] != 0u) { is64 = 0; break; }
        g_is64 = is64;
    }
}

// ---------------------------------------------------------------------------
// Precompute: T[n][256] = fp16([emb@W1[:128]+b1 | emb@W1[128:]])
// Single-pass fp16 MMA, fp32 accumulate, b1 folded into acc init.
// BLOCK_M=64, 8 warps = 2(M) x 4(N), two 128-col passes over fused N=256.
// (256,4): 4 CTAs/SM (32 warps) — measured best occupancy point.
// Per pass: [bar, MMA, bar, copy-next-pair || epilogue].
// Epilogue: 3-shfl quad transpose -> coalesced STG.128.
// ---------------------------------------------------------------------------
#define BLOCK_M 64
#define SA_ELE (BLOCK_M * PITCH)           // 4352 b32
#define SB_PAIR (2 * SB_ELE)               // 8704 b32 (two 64-col tiles)
#define SM_B1_OFF (SA_ELE + SB_PAIR)       // b32 offset of b1 (128 floats)
#define SMEM_BYTES ((SA_ELE + SB_PAIR + HID) * 4)   // 52736 B -> 4 CTAs/SM

__global__ void __launch_bounds__(256, 4) precompute_kernel(
    const float* __restrict__ emb, const float* __restrict__ b1, int n_nodes)
{
    extern __shared__ uint32_t sm[];
    uint32_t* sA = sm;
    uint32_t* sB = sm + SA_ELE;            // pair of B tiles
    float* sb1 = reinterpret_cast<float*>(sm + SM_B1_OFF);

    const int tid = threadIdx.x;
    const int m0 = blockIdx.x * BLOCK_M;

    if (tid < HID) sb1[tid] = b1[tid];

    // ---- A tile: 64 rows x 128 K floats -> fp16 pairs (once) ----
    for (int i = tid; i < BLOCK_M * (HID / 4); i += 256) {
        int row = i >> 5;
        int c4 = (i & 31) * 4;
        float4 v = make_float4(0.f, 0.f, 0.f, 0.f);
        if (m0 + row < n_nodes)
            v = *reinterpret_cast<const float4*>(emb + (size_t)(m0 + row) * HID + c4);
        int base = row * PITCH + c4 / 2;   // even -> 8B aligned
        *reinterpret_cast<uint2*>(sA + base) =
            make_uint2(pack_h2(v.x, v.y), pack_h2(v.z, v.w));
    }

    // ---- copy B pair 0 (tiles 0,1) ----
    {
        const uint4* s = reinterpret_cast<const uint4*>(g_sB);
        uint4* d = reinterpret_cast<uint4*>(sB);
        for (int i = tid; i < SB_PAIR / 4; i += 256)
            d[i] = s[i];
    }

    const int warp = tid >> 5, lane = tid & 31;
    const int wm = warp & 1;    // 2 M slabs of 32 rows
    const int wn = warp >> 1;   // 4 N slabs of 32 cols (128 cols per pass)
    const int gid = lane >> 2, tig = lane & 3;

    const int a_row = (lane & 15);
    const int a_kb  = (lane >> 4) * 4;
    const int b_n  = (lane & 7) + (lane >> 4) * 8;
    const int b_kb = ((lane >> 3) & 1) * 4;

    const uint32_t sA_a = smem_u32(sA), sB_a = smem_u32(sB);
    const uint32_t sBslab_a = sB_a + (uint32_t)((wn >> 1) * SB_ELE
                                                + (wn & 1) * 32 * PITCH) * 4u;

#pragma unroll 1
    for (int j = 0; j < 2; j++) {
        __syncthreads();   // B pair j visible to all warps

        // ---- acc init: b1 for cols < 128 (j==0), else 0 ----
        float acc[2][4][4];
#pragma unroll
        for (int ni = 0; ni < 4; ni++) {
            float c0 = 0.f, c1 = 0.f;
            if (j == 0) {
                int gcol = wn * 32 + ni * 8 + 2 * tig;
                float2 bb = *reinterpret_cast<const float2*>(sb1 + gcol);
                c0 = bb.x; c1 = bb.y;
            }
#pragma unroll
            for (int mi = 0; mi < 2; mi++) {
                acc[mi][ni][0] = c0; acc[mi][ni][1] = c1;
                acc[mi][ni][2] = c0; acc[mi][ni][3] = c1;
            }
        }

#pragma unroll
        for (int ks = 0; ks < HID / 16; ks++) {
            const int kb0 = ks * 8;
            uint32_t af[2][4], bf[2][4];
#pragma unroll
            for (int mi = 0; mi < 2; mi++) {
                uint32_t off = ((wm * 32 + mi * 16 + a_row) * PITCH + kb0 + a_kb) * 4u;
                ldsm_x4(af[mi], sA_a + off);
            }
#pragma unroll
            for (int pr = 0; pr < 2; pr++) {
                uint32_t off = ((pr * 16 + b_n) * PITCH + kb0 + b_kb) * 4u;
                ldsm_x4(bf[pr], sBslab_a + off);
            }
#pragma unroll
            for (int mi = 0; mi < 2; mi++)
#pragma unroll
                for (int ni = 0; ni < 4; ni++)
                    mma_f16(acc[mi][ni], af[mi], &bf[ni >> 1][(ni & 1) * 2]);
        }

        __syncthreads();   // all warps' reads of pair j complete

        // ---- copy B pair 1 (overlaps the epilogue STGs below) ----
        if (j == 0) {
            const uint4* s = reinterpret_cast<const uint4*>(g_sB + SB_PAIR);
            uint4* d = reinterpret_cast<uint4*>(sB);
            for (int i = tid; i < SB_PAIR / 4; i += 256)
                d[i] = s[i];
        }

        // ---- epilogue: pack fp16, quad-transpose, coalesced STG.128 ----
        const int cb = j * 128 + wn * 32 + 8 * tig;
#pragma unroll
        for (int mi = 0; mi < 2; mi++) {
#pragma unroll
            for (int rh = 0; rh < 2; rh++) {
                uint32_t v[4];   // v[ni] = half2(acc[mi][ni][2rh], [2rh+1])
#pragma unroll
                for (int ni = 0; ni < 4; ni++)
                    v[ni] = pack_h2(acc[mi][ni][2 * rh], acc[mi][ni][2 * rh + 1]);
                uint32_t r1 = __shfl_xor_sync(0xFFFFFFFFu, v[tig ^ 1], 1);
                uint32_t r2 = __shfl_xor_sync(0xFFFFFFFFu, v[tig ^ 2], 2);
                uint32_t r3 = __shfl_xor_sync(0xFFFFFFFFu, v[tig ^ 3], 3);
                uint32_t ww[4];
                ww[tig] = v[tig];
                ww[tig ^ 1] = r1;
                ww[tig ^ 2] = r2;
                ww[tig ^ 3] = r3;
                int row = m0 + wm * 32 + mi * 16 + rh * 8 + gid;
                if (row < n_nodes) {
                    *reinterpret_cast<uint4*>(&g_table[(size_t)row * 256 + cb]) =
                        make_uint4(ww[0], ww[1], ww[2], ww[3]);
                }
            }
        }
    }
}

// ---------------------------------------------------------------------------
// Edge kernel: 8 edges per warp (half-warp owns 4 consecutive edges).
// Indices loaded evict-first (.cs, read-once); table gathers .nc (reused,
// keep in L1/L2); output stored streaming (.cs, write-once) so it never
// evicts table lines. hfma2_relu fused add+relu, fp32 reduce:
// 2 butterfly rounds + 3-shfl transpose-reduce, per-lane 4B stores.
// ---------------------------------------------------------------------------
__device__ __forceinline__ __half2 u2h(uint32_t x) {
    return *reinterpret_cast<__half2*>(&x);
}

__device__ __forceinline__ float dot8_relu(uint4 a, uint4 c, uint4 w) {
    const __half2 one = __float2half2_rn(1.f);
    __half2 r0 = __hfma2_relu(u2h(a.x), one, u2h(c.x));
    __half2 r1 = __hfma2_relu(u2h(a.y), one, u2h(c.y));
    __half2 r2 = __hfma2_relu(u2h(a.z), one, u2h(c.z));
    __half2 r3 = __hfma2_relu(u2h(a.w), one, u2h(c.w));
    __half2 p0 = __hmul2(r0, u2h(w.x));
    p0 = __hfma2(r1, u2h(w.y), p0);
    __half2 p1 = __hmul2(r2, u2h(w.z));
    p1 = __hfma2(r3, u2h(w.w), p1);
    float2 f0 = __half22float2(p0);
    float2 f1 = __half22float2(p1);
    return (f0.x + f0.y) + (f1.x + f1.y);
}

__global__ void __launch_bounds__(256) edge_kernel(
    const void* __restrict__ srcv, const void* __restrict__ tgtv,
    const float* __restrict__ b2, float* __restrict__ out, int E)
{
    int gw = (int)((blockIdx.x * blockDim.x + threadIdx.x) >> 5);
    int base = gw * 8;
    if (base >= E) return;
    int lane = threadIdx.x & 31;
    int half = lane >> 4, l16 = lane & 15;
    int tig = lane & 3;

    int e0 = base + half * 4;             // this half's first edge (mult of 4)
    bool full = (e0 + 4 <= E);

    uint32_t s[4], t[4];
    if (g_is64) {
        const long long* sp = (const long long*)srcv;
        const long long* tp = (const long long*)tgtv;
        if (full) {
            uint4 s01 = ldg_cs_v4(sp + e0);
            uint4 s23 = ldg_cs_v4(sp + e0 + 2);
            uint4 t01 = ldg_cs_v4(tp + e0);
            uint4 t23 = ldg_cs_v4(tp + e0 + 2);
            s[0] = s01.x; s[1] = s01.z; s[2] = s23.x; s[3] = s23.z;
            t[0] = t01.x; t[1] = t01.z; t[2] = t23.x; t[3] = t23.z;
        } else {
#pragma unroll
            for (int e = 0; e < 4; e++) {
                int idx = (e0 + e < E) ? e0 + e : E - 1;
                s[e] = (uint32_t)sp[idx];
                t[e] = (uint32_t)tp[idx];
            }
        }
    } else {
        const int* sp = (const int*)srcv;
        const int* tp = (const int*)tgtv;
        if (full) {
            uint4 sv = ldg_cs_v4(sp + e0);
            uint4 tv = ldg_cs_v4(tp + e0);
            s[0] = sv.x; s[1] = sv.y; s[2] = sv.z; s[3] = sv.w;
            t[0] = tv.x; t[1] = tv.y; t[2] = tv.z; t[3] = tv.w;
        } else {
#pragma unroll
            for (int e = 0; e < 4; e++) {
                int idx = (e0 + e < E) ? e0 + e : E - 1;
                s[e] = (uint32_t)sp[idx];
                t[e] = (uint32_t)tp[idx];
            }
        }
    }

    const __half* tab = g_table;
    const uint32_t col = (uint32_t)(l16 * 8);
    // all 8 gathers issued back-to-back (ordered volatile asm -> MLP=8)
    uint4 A[4], C[4];
#pragma unroll
    for (int e = 0; e < 4; e++)
        A[e] = ldg_nc_v4(tab + s[e] * 256u + col);
#pragma unroll
    for (int e = 0; e < 4; e++)
        C[e] = ldg_nc_v4(tab + t[e] * 256u + 128u + col);
    const uint4 w = __ldg(reinterpret_cast<const uint4*>(g_W2h + col));

    float sum[4];
#pragma unroll
    for (int e = 0; e < 4; e++)
        sum[e] = dot8_relu(A[e], C[e], w);

    // 2 butterfly rounds: each lane ends with partial over lanes == l16 (mod 4)
#pragma unroll
    for (int off = 8; off >= 4; off >>= 1) {
#pragma unroll
        for (int e = 0; e < 4; e++)
            sum[e] += __shfl_xor_sync(0xFFFFFFFFu, sum[e], off);
    }
    // transpose-reduce across the quad: lane tig accumulates edge tig's total
    float tot = sum[tig];
    tot += __shfl_xor_sync(0xFFFFFFFFu, sum[tig ^ 1], 1);
    tot += __shfl_xor_sync(0xFFFFFFFFu, sum[tig ^ 2], 2);
    tot += __shfl_xor_sync(0xFFFFFFFFu, sum[tig ^ 3], 3);

    if (l16 < 4) {
        int eo = e0 + tig;
        if (eo < E) stg_cs_f32(out + eo, tot + __ldg(b2));
    }
}

// ---------------------------------------------------------------------------
// launch
// ---------------------------------------------------------------------------
extern "C" void kernel_launch(void* const* d_in, const int* in_sizes, int n_in,
                              void* d_out, int out_size)
{
    const float* emb = (const float*)d_in[0];
    const void* src = d_in[1];
    const void* tgt = d_in[2];

    int base = (n_in > 3 && in_sizes[3] == 2 * HID * HID) ? 3 : 4;
    const float* W1 = (const float*)d_in[base];
    const float* b1 = (const float*)d_in[base + 1];
    const float* W2 = (const float*)d_in[base + 2];
    const float* b2 = (const float*)d_in[base + 3];

    int n_nodes = in_sizes[0] / HID;
    int E = in_sizes[1];

    prep_kernel<<<64, 256>>>(W1, W2, (const uint32_t*)src);

    cudaFuncSetAttribute(precompute_kernel,
                         cudaFuncAttributeMaxDynamicSharedMemorySize, SMEM_BYTES);
    int pgrid = (n_nodes + BLOCK_M - 1) / BLOCK_M;
    precompute_kernel<<<pgrid, 256, SMEM_BYTES>>>(emb, b1, n_nodes);

    // 8 warps/block, 8 edges/warp
    int warps_needed = (E + 7) / 8;
    int nblocks = (warps_needed + 7) / 8;
    edge_kernel<<<nblocks, 256>>>(src, tgt, b2, (float*)d_out, E);
}